// round 15
// baseline (speedup 1.0000x reference)
#include <cuda_runtime.h>
#include <cstdint>

#define BATCH 16
#define TLEN  256
#define HID   1024
#define EMB   512
#define VOC   32000
#define GATES 3072
#define ROWS  4096          // BATCH*TLEN

// ---------------- device scratch (no allocations allowed) ----------------
__device__ float g_xW[ROWS * GATES];        // 50.3 MB : x@Wi + bi (fp32)
__device__ float g_apk[ROWS * HID];         // 16.8 MB : hidden states, FRAGMENT-PACKED tf32
__device__ float g_h[2][BATCH * HID];       // double-buffered h (tf32 bits)
__device__ float g_xt[ROWS * EMB];          // 8.4 MB  : gathered embeddings, tf32
__device__ float g_wip[EMB * GATES];        // 6.3 MB  : Wi tf32
__device__ float g_wopk[VOC * HID];         // 131 MB  : Wo FRAGMENT-PACKED tf32
__device__ uint4 g_whp[128 * 8 * 3 * 8 * 32]; // 12.6 MB: Wh packed mma fragments
__device__ unsigned g_bar_count = 0;
__device__ volatile unsigned g_bar_release = 0;  // monotonic epoch

// ---------------- helpers ----------------
__device__ __forceinline__ unsigned f2tf32(float f) {
    unsigned u;
    asm("cvt.rna.tf32.f32 %0, %1;" : "=r"(u) : "f"(f));
    return u;
}
__device__ __forceinline__ void mma_tf32(float c[4], const unsigned a[4],
                                         unsigned b0, unsigned b1) {
    asm volatile(
        "mma.sync.aligned.m16n8k8.row.col.f32.tf32.tf32.f32 "
        "{%0,%1,%2,%3}, {%4,%5,%6,%7}, {%8,%9}, {%0,%1,%2,%3};"
        : "+f"(c[0]), "+f"(c[1]), "+f"(c[2]), "+f"(c[3])
        : "r"(a[0]), "r"(a[1]), "r"(a[2]), "r"(a[3]), "r"(b0), "r"(b1));
}
__device__ __forceinline__ void cp16(uint32_t dst, const void* src) {
    asm volatile("cp.async.cg.shared.global [%0], [%1], 16;" :: "r"(dst), "l"(src));
}
__device__ __forceinline__ unsigned ld_acq(volatile unsigned* p) {
    unsigned v;
    asm volatile("ld.global.acquire.gpu.b32 %0, [%1];" : "=r"(v) : "l"((unsigned*)p));
    return v;
}
__device__ __forceinline__ void st_rel(volatile unsigned* p, unsigned v) {
    asm volatile("st.global.release.gpu.b32 [%0], %1;" :: "l"((unsigned*)p), "r"(v));
}
__device__ __forceinline__ uint32_t smem_u32(const void* p) {
    return (uint32_t)__cvta_generic_to_shared(p);
}

// ---------------- fragment-packed layout indexers (big GEMM) ----------------
// A tile 128x32 per (tm,tk): chunk = [warpM(2)][lane(32)][64 words], lane-rotated.
__device__ __forceinline__ int apack_idx(int m, int k) {
    int tm = m >> 7, r = m & 127;
    int tk = k >> 5, kk = k & 31;
    int wM = r >> 6, r6 = r & 63;
    int mf = r6 >> 4, hf = (r6 >> 3) & 1, gd = r6 & 7;
    int ks = kk >> 3, c8 = kk & 7;
    int qd = c8 >> 2, tg = c8 & 3;
    int lane = gd * 4 + tg;
    int w = hf + 2 * qd;
    int swz = (ks * 16 + mf * 4 + lane * 4) & 63;
    return (((tm * 32 + tk) * 2 + wM) * 32 + lane) * 64 + swz + w;
}
// B tile 32x256 per (tn,tk): chunk = [warpN(4)][lane(32)][64 words], lane-rotated.
__device__ __forceinline__ int bpack_idx(int n, int k) {
    int tn = n >> 8, n8 = n & 255;
    int wN = n8 >> 6, n6 = n8 & 63;
    int nf = n6 >> 3, gd = n6 & 7;
    int kk = k & 31, tk = k >> 5;
    int ks = kk >> 3, c8 = kk & 7;
    int s = c8 >> 2, tg = c8 & 3;
    int lane = gd * 4 + tg;
    int nfp = nf >> 1;
    int w = (nf & 1) * 2 + s;
    int swz = (ks * 16 + nfp * 4 + lane * 4) & 63;
    return (((tn * 32 + tk) * 4 + wN) * 32 + lane) * 64 + swz + w;
}

// ---------------- prep kernels ----------------
__global__ void cvt_tf32_k(const float4* __restrict__ in, float4* __restrict__ out, int n4) {
    int i = blockIdx.x * 256 + threadIdx.x;
    if (i >= n4) return;
    float4 v = in[i];
    v.x = __uint_as_float(f2tf32(v.x));
    v.y = __uint_as_float(f2tf32(v.y));
    v.z = __uint_as_float(f2tf32(v.z));
    v.w = __uint_as_float(f2tf32(v.w));
    out[i] = v;
}

__global__ void gather_x_k(const float4* __restrict__ embed, const int* __restrict__ targets,
                           float4* __restrict__ xt) {
    int i = blockIdx.x * 256 + threadIdx.x;
    int m = i >> 7, e = i & 127;
    int row = __ldg(targets + m);
    float4 v = embed[(size_t)row * 128 + e];
    v.x = __uint_as_float(f2tf32(v.x));
    v.y = __uint_as_float(f2tf32(v.y));
    v.z = __uint_as_float(f2tf32(v.z));
    v.w = __uint_as_float(f2tf32(v.w));
    xt[(size_t)m * 128 + e] = v;
}

__global__ void pack_wh_k(const float* __restrict__ Wh, uint4* __restrict__ whp) {
    int c = blockIdx.x * 256 + threadIdx.x;
    int lane = c & 31, t1 = c >> 5;
    int sp = t1 & 7; t1 >>= 3;
    int j = t1 % 3; t1 /= 3;
    int kw = t1 & 7, nb = t1 >> 3;
    int tig = lane & 3, gid = lane >> 2;
    int n  = j * 1024 + nb * 8 + gid;
    int kb = kw * 128 + sp * 16 + tig;
    uint4 v;
    v.x = f2tf32(Wh[(size_t)kb * GATES + n]);
    v.y = f2tf32(Wh[(size_t)(kb + 4) * GATES + n]);
    v.z = f2tf32(Wh[(size_t)(kb + 8) * GATES + n]);
    v.w = f2tf32(Wh[(size_t)(kb + 12) * GATES + n]);
    whp[c] = v;
}

// Wo [H,V] row-major -> fragment-packed [tn][tk][warpN][lane][64] (tf32 bits)
__global__ void pack_wo_k(const float* __restrict__ Wo, float* __restrict__ Bpk) {
    long long i = (long long)blockIdx.x * 256 + threadIdx.x;   // 32.768M elems
    if (i >= (long long)VOC * HID) return;
    int k = (int)(i / VOC);
    int n = (int)(i - (long long)k * VOC);
    Bpk[bpack_idx(n, k)] = __uint_as_float(f2tf32(Wo[i]));
}

// ---------------------------------------------------------------------------
// Legacy pipelined tf32 GEMM (kept for the small xW GEMM, K=512)
// ---------------------------------------------------------------------------
#define ASZ 4608
#define BSZ 4224

__global__ __launch_bounds__(256) void gemm_pipe(
    const float* __restrict__ A, const float* __restrict__ B,
    const float* __restrict__ bias, float* __restrict__ C, int N, int K)
{
    extern __shared__ unsigned gsm[];
    unsigned* As = gsm;
    unsigned* Bs = gsm + 3 * ASZ;
    const uint32_t as_base = smem_u32(As);
    const uint32_t bs_base = smem_u32(Bs);

    const int t  = threadIdx.x;
    const int m0 = blockIdx.x * 128;
    const int n0 = blockIdx.y * 128;
    const int warp = t >> 5, lane = t & 31;
    const int gid = lane >> 2, tig = lane & 3;
    const int wm = (warp >> 2) * 64, wn = (warp & 3) * 32;
    const int ar  = t >> 3;
    const int ac  = (t & 7) * 4;
    const int bkr = t >> 5;
    const int bc  = (t & 31) * 4;
    const int NT = K / 32;

    float acc[4][4][4];
#pragma unroll
    for (int mf = 0; mf < 4; mf++)
#pragma unroll
        for (int nf = 0; nf < 4; nf++)
#pragma unroll
            for (int i = 0; i < 4; i++) acc[mf][nf][i] = 0.f;

#pragma unroll
    for (int pre = 0; pre < 2; pre++) {
        int k0 = pre * 32;
#pragma unroll
        for (int p = 0; p < 4; p++) {
            int r = ar + 32 * p;
            cp16(as_base + (uint32_t)(pre * ASZ + r * 36 + ac) * 4,
                 A + (size_t)(m0 + r) * K + k0 + ac);
        }
#pragma unroll
        for (int p = 0; p < 4; p++) {
            int kr = bkr + 8 * p;
            cp16(bs_base + (uint32_t)(pre * BSZ + kr * 132 + bc) * 4,
                 B + (size_t)(k0 + kr) * N + n0 + bc);
        }
        asm volatile("cp.async.commit_group;");
    }

    for (int kt = 0; kt < NT; kt++) {
        asm volatile("cp.async.wait_group 1;");
        __syncthreads();
        int ft = kt + 2;
        if (ft < NT) {
            int st = ft % 3, k0 = ft * 32;
#pragma unroll
            for (int p = 0; p < 4; p++) {
                int r = ar + 32 * p;
                cp16(as_base + (uint32_t)(st * ASZ + r * 36 + ac) * 4,
                     A + (size_t)(m0 + r) * K + k0 + ac);
            }
#pragma unroll
            for (int p = 0; p < 4; p++) {
                int kr = bkr + 8 * p;
                cp16(bs_base + (uint32_t)(st * BSZ + kr * 132 + bc) * 4,
                     B + (size_t)(k0 + kr) * N + n0 + bc);
            }
        }
        asm volatile("cp.async.commit_group;");

        const unsigned* Ab = As + (kt % 3) * ASZ;
        const unsigned* Bb = Bs + (kt % 3) * BSZ;
#pragma unroll
        for (int ks = 0; ks < 4; ks++) {
            const int kk = ks * 8;
            unsigned af[4][4], bf[4][2];
#pragma unroll
            for (int mf = 0; mf < 4; mf++) {
                int r = wm + mf * 16 + gid;
                af[mf][0] = Ab[r * 36 + kk + tig];
                af[mf][1] = Ab[(r + 8) * 36 + kk + tig];
                af[mf][2] = Ab[r * 36 + kk + tig + 4];
                af[mf][3] = Ab[(r + 8) * 36 + kk + tig + 4];
            }
#pragma unroll
            for (int nf = 0; nf < 4; nf++) {
                int cn = wn + nf * 8 + gid;
                bf[nf][0] = Bb[(kk + tig) * 132 + cn];
                bf[nf][1] = Bb[(kk + tig + 4) * 132 + cn];
            }
#pragma unroll
            for (int mf = 0; mf < 4; mf++)
#pragma unroll
                for (int nf = 0; nf < 4; nf++)
                    mma_tf32(acc[mf][nf], af[mf], bf[nf][0], bf[nf][1]);
        }
    }

#pragma unroll
    for (int mf = 0; mf < 4; mf++) {
        int row = m0 + wm + mf * 16 + gid;
#pragma unroll
        for (int nf = 0; nf < 4; nf++) {
            int col = n0 + wn + nf * 8 + tig * 2;
            float b0 = bias ? bias[col] : 0.f;
            float b1 = bias ? bias[col + 1] : 0.f;
            float2 v0 = make_float2(acc[mf][nf][0] + b0, acc[mf][nf][1] + b1);
            float2 v1 = make_float2(acc[mf][nf][2] + b0, acc[mf][nf][3] + b1);
            *reinterpret_cast<float2*>(C + (size_t)row * N + col)       = v0;
            *reinterpret_cast<float2*>(C + (size_t)(row + 8) * N + col) = v1;
        }
    }
}

// ---------------------------------------------------------------------------
// Big output GEMM, fragment-packed operands, LDS.128 fragment loads.
// C[4096,32000] = A[4096,1024] @ Wo + bo.  Block tile 128x256x32, 8 warps
// (2 M x 4 N), warp tile 64x64, acc 128 regs. 3-stage cp.async pipeline.
// ---------------------------------------------------------------------------
#define GB_ASTG 4096            // words per A stage (16KB)
#define GB_BSTG 8192            // words per B stage (32KB)
#define GB_STG  (GB_ASTG + GB_BSTG)
#define GB_SMEM (3 * GB_STG * 4)   // 147456 B
#define GB_NT   32              // 1024/32 k-tiles

__global__ __launch_bounds__(256, 1) void gemm_big(
    const float* __restrict__ Apk, const float* __restrict__ Bpk,
    const float* __restrict__ bias, float* __restrict__ C)
{
    extern __shared__ unsigned gbs[];
    const uint32_t sbase = smem_u32(gbs);

    const int tid  = threadIdx.x;
    const int lane = tid & 31;
    const int warp = tid >> 5;
    const int wM   = warp & 1;        // 0..1
    const int wN   = warp >> 1;       // 0..3
    const int mt   = blockIdx.x;      // 0..31
    const int nt   = blockIdx.y;      // 0..124

    float acc[4][8][4];
#pragma unroll
    for (int mf = 0; mf < 4; mf++)
#pragma unroll
        for (int nf = 0; nf < 8; nf++)
#pragma unroll
            for (int i = 0; i < 4; i++) acc[mf][nf][i] = 0.f;

    const float* abase = Apk + (size_t)(mt * 32) * GB_ASTG + tid * 16;
    const float* bbase = Bpk + (size_t)(nt * 32) * GB_BSTG + tid * 32;

    // prologue: stages 0,1
#pragma unroll
    for (int pre = 0; pre < 2; pre++) {
        uint32_t sa = sbase + (uint32_t)(pre * GB_STG + tid * 16) * 4;
        uint32_t sb = sbase + (uint32_t)(pre * GB_STG + GB_ASTG + tid * 32) * 4;
        const float* ga = abase + (size_t)pre * GB_ASTG;
        const float* gb = bbase + (size_t)pre * GB_BSTG;
#pragma unroll
        for (int j = 0; j < 4; j++) cp16(sa + j * 16, ga + j * 4);
#pragma unroll
        for (int j = 0; j < 8; j++) cp16(sb + j * 16, gb + j * 4);
        asm volatile("cp.async.commit_group;");
    }

    const int aoff = (wM * 32 + lane) * 64;
    const int boff = (wN * 32 + lane) * 64;
    const int rot  = lane * 4;

    for (int kt = 0; kt < GB_NT; kt++) {
        asm volatile("cp.async.wait_group 1;");
        __syncthreads();

        int ft = kt + 2;
        if (ft < GB_NT) {
            int st = ft % 3;
            uint32_t sa = sbase + (uint32_t)(st * GB_STG + tid * 16) * 4;
            uint32_t sb = sbase + (uint32_t)(st * GB_STG + GB_ASTG + tid * 32) * 4;
            const float* ga = abase + (size_t)ft * GB_ASTG;
            const float* gb = bbase + (size_t)ft * GB_BSTG;
#pragma unroll
            for (int j = 0; j < 4; j++) cp16(sa + j * 16, ga + j * 4);
#pragma unroll
            for (int j = 0; j < 8; j++) cp16(sb + j * 16, gb + j * 4);
        }
        asm volatile("cp.async.commit_group;");

        const unsigned* Ab = gbs + (kt % 3) * GB_STG + aoff;
        const unsigned* Bb = gbs + (kt % 3) * GB_STG + GB_ASTG + boff;

#pragma unroll
        for (int ks = 0; ks < 4; ks++) {
            uint4 av[4], bv[4];
#pragma unroll
            for (int mf = 0; mf < 4; mf++)
                av[mf] = *reinterpret_cast<const uint4*>(
                    Ab + ((ks * 16 + mf * 4 + rot) & 63));
#pragma unroll
            for (int np = 0; np < 4; np++)
                bv[np] = *reinterpret_cast<const uint4*>(
                    Bb + ((ks * 16 + np * 4 + rot) & 63));
#pragma unroll
            for (int mf = 0; mf < 4; mf++) {
                unsigned af[4] = {av[mf].x, av[mf].y, av[mf].z, av[mf].w};
#pragma unroll
                for (int np = 0; np < 4; np++) {
                    mma_tf32(acc[mf][2 * np],     af, bv[np].x, bv[np].y);
                    mma_tf32(acc[mf][2 * np + 1], af, bv[np].z, bv[np].w);
                }
            }
        }
    }

    // epilogue
    const int gid = lane >> 2, tig = lane & 3;
#pragma unroll
    for (int mf = 0; mf < 4; mf++) {
        int row = mt * 128 + wM * 64 + mf * 16 + gid;
        float* c0 = C + (size_t)row * VOC;
        float* c1 = C + (size_t)(row + 8) * VOC;
#pragma unroll
        for (int nf = 0; nf < 8; nf++) {
            int col = nt * 256 + wN * 64 + nf * 8 + tig * 2;
            float b0 = bias[col], b1 = bias[col + 1];
            *reinterpret_cast<float2*>(c0 + col) =
                make_float2(acc[mf][nf][0] + b0, acc[mf][nf][1] + b1);
            *reinterpret_cast<float2*>(c1 + col) =
                make_float2(acc[mf][nf][2] + b0, acc[mf][nf][3] + b1);
        }
    }
}

// ---------------------------------------------------------------------------
// Tensor-core GRU recurrence (tf32 h exchange, fp32 register carry).
// Writes hidden states directly in fragment-packed order for gemm_big.
// ---------------------------------------------------------------------------
#define RNB 128
#define RNT 256
#define HSH 1028
#define WGT_WORDS (8*3*8*32*4)
#define PART_STRIDE 9

__global__ __launch_bounds__(RNT) void gru_rec(
    const float* __restrict__ enc, const uint4* __restrict__ whp,
    const float* __restrict__ bhn, const float* __restrict__ xW)
{
    extern __shared__ unsigned smu[];
    unsigned* sh_wgt = smu;
    float* sh_h      = (float*)(smu + WGT_WORDS);
    float* sh_part   = sh_h + BATCH * HSH;

    const int tid  = threadIdx.x;
    const int warp = tid >> 5;
    const int lane = tid & 31;
    const int gid  = lane >> 2, tig = lane & 3;
    const int u0   = blockIdx.x * 8;

    {
        const uint4* src = whp + (size_t)blockIdx.x * (WGT_WORDS / 4);
        uint4* dst = (uint4*)sh_wgt;
        for (int i = tid; i < WGT_WORDS / 4; i += RNT) dst[i] = src[i];
    }
    for (int idx = tid; idx < BATCH * HID; idx += RNT)
        sh_h[(idx >> 10) * HSH + (idx & 1023)] =
            __uint_as_float(f2tf32(enc[idx]));

    float hreg = 0.f;
    const int ob = tid >> 3, ou = tid & 7;
    if (tid < 128) hreg = enc[ob * HID + u0 + ou];
    __syncthreads();

    unsigned a[16][4];
#pragma unroll
    for (int s = 0; s < 16; s++) {
        int k = warp * 128 + s * 8 + tig;
        a[s][0] = __float_as_uint(sh_h[gid * HSH + k]);
        a[s][1] = __float_as_uint(sh_h[(gid + 8) * HSH + k]);
        a[s][2] = __float_as_uint(sh_h[gid * HSH + k + 4]);
        a[s][3] = __float_as_uint(sh_h[(gid + 8) * HSH + k + 4]);
    }

    const uint4* wp = (const uint4*)sh_wgt + warp * (3 * 8 * 32);

    for (int t = 0; t < TLEN; t++) {
        float xr = 0.f, xz = 0.f, xn = 0.f;
        if (tid < 128) {
            const float* xrow = xW + (size_t)(ob * TLEN + t) * GATES;
            int j = u0 + ou;
            xr = __ldg(xrow + j);
            xz = __ldg(xrow + HID + j);
            xn = __ldg(xrow + 2 * HID + j);
        }

        float c[3][4];
#pragma unroll
        for (int j = 0; j < 3; j++)
#pragma unroll
            for (int i = 0; i < 4; i++) c[j][i] = 0.f;

#pragma unroll
        for (int j = 0; j < 3; j++)
#pragma unroll
            for (int sp = 0; sp < 8; sp++) {
                uint4 bv = wp[(j * 8 + sp) * 32 + lane];
                mma_tf32(c[j], a[2 * sp],     bv.x, bv.y);
                mma_tf32(c[j], a[2 * sp + 1], bv.z, bv.w);
            }

#pragma unroll
        for (int j = 0; j < 3; j++) {
            sh_part[((j * 16 + gid) * 8 + tig * 2)         * PART_STRIDE + warp] = c[j][0];
            sh_part[((j * 16 + gid) * 8 + tig * 2 + 1)     * PART_STRIDE + warp] = c[j][1];
            sh_part[((j * 16 + gid + 8) * 8 + tig * 2)     * PART_STRIDE + warp] = c[j][2];
            sh_part[((j * 16 + gid + 8) * 8 + tig * 2 + 1) * PART_STRIDE + warp] = c[j][3];
        }
        __syncthreads();

        if (tid < 128) {
            float hr = 0.f, hz = 0.f, hn = 0.f;
#pragma unroll
            for (int q = 0; q < 8; q++) {
                hr += sh_part[((0 * 16 + ob) * 8 + ou) * PART_STRIDE + q];
                hz += sh_part[((1 * 16 + ob) * 8 + ou) * PART_STRIDE + q];
                hn += sh_part[((2 * 16 + ob) * 8 + ou) * PART_STRIDE + q];
            }
            int j = u0 + ou;
            float r  = 1.f / (1.f + expf(-(xr + hr)));
            float z  = 1.f / (1.f + expf(-(xz + hz)));
            float nn = tanhf(xn + r * (hn + bhn[j]));
            float hnew = (1.f - z) * nn + z * hreg;
            hreg = hnew;
            float htf = __uint_as_float(f2tf32(hnew));
            g_apk[apack_idx(ob * TLEN + t, j)] = htf;   // fragment-packed
            g_h[t & 1][ob * HID + j] = htf;
        }
        if (t == TLEN - 1) break;

        // ---- grid barrier ----
        __threadfence();
        __syncthreads();
        if (tid == 0) {
            unsigned epoch = g_bar_release;
            unsigned old = atomicAdd(&g_bar_count, 1);
            if (old == gridDim.x - 1) {
                g_bar_count = 0;
                __threadfence();
                st_rel(&g_bar_release, epoch + 1);
            } else {
                while (ld_acq(&g_bar_release) == epoch) { }
            }
        }
        __syncthreads();

        // ---- all-gather h (tf32 bits), rebuild fragments ----
        const float4* src = reinterpret_cast<const float4*>(&g_h[t & 1][0]);
        for (int i = tid; i < BATCH * HID / 4; i += RNT) {
            float4 v = __ldcg(&src[i]);
            int b = i >> 8, kk = (i & 255) << 2;
            *reinterpret_cast<float4*>(&sh_h[b * HSH + kk]) = v;
        }
        __syncthreads();
#pragma unroll
        for (int s = 0; s < 16; s++) {
            int k = warp * 128 + s * 8 + tig;
            a[s][0] = __float_as_uint(sh_h[gid * HSH + k]);
            a[s][1] = __float_as_uint(sh_h[(gid + 8) * HSH + k]);
            a[s][2] = __float_as_uint(sh_h[gid * HSH + k + 4]);
            a[s][3] = __float_as_uint(sh_h[(gid + 8) * HSH + k + 4]);
        }
    }
}

// ---------------------------------------------------------------------------
extern "C" void kernel_launch(void* const* d_in, const int* in_sizes, int n_in,
                              void* d_out, int out_size)
{
    const float *enc = nullptr, *embed = nullptr, *Wi = nullptr, *Wh = nullptr;
    const float *bi = nullptr, *bhn = nullptr, *Wo = nullptr, *bo = nullptr;
    const int* targets = nullptr;

    for (int i = 0; i < n_in; i++) {
        switch (in_sizes[i]) {
            case BATCH * HID:  enc     = (const float*)d_in[i]; break;
            case BATCH * TLEN: targets = (const int*)  d_in[i]; break;
            case VOC * EMB:    embed   = (const float*)d_in[i]; break;
            case EMB * GATES:  Wi      = (const float*)d_in[i]; break;
            case HID * GATES:  Wh      = (const float*)d_in[i]; break;
            case GATES:        bi      = (const float*)d_in[i]; break;
            case HID:          bhn     = (const float*)d_in[i]; break;
            case HID * VOC:    Wo      = (const float*)d_in[i]; break;
            case VOC:          bo      = (const float*)d_in[i]; break;
            default: break;
        }
    }

    float *xW, *apk, *xt, *wip, *wopk;
    uint4* whp;
    cudaGetSymbolAddress((void**)&xW,   g_xW);
    cudaGetSymbolAddress((void**)&apk,  g_apk);
    cudaGetSymbolAddress((void**)&xt,   g_xt);
    cudaGetSymbolAddress((void**)&wip,  g_wip);
    cudaGetSymbolAddress((void**)&wopk, g_wopk);
    cudaGetSymbolAddress((void**)&whp,  g_whp);

    const int gemm_smem = 3 * (ASZ + BSZ) * 4;
    const int rec_smem  = (WGT_WORDS + BATCH * HSH + 384 * PART_STRIDE) * 4;
    cudaFuncSetAttribute(gemm_pipe, cudaFuncAttributeMaxDynamicSharedMemorySize, gemm_smem);
    cudaFuncSetAttribute(gru_rec,   cudaFuncAttributeMaxDynamicSharedMemorySize, rec_smem);
    cudaFuncSetAttribute(gemm_big,  cudaFuncAttributeMaxDynamicSharedMemorySize, GB_SMEM);

    // ---- prep ----
    cvt_tf32_k<<<(EMB * GATES / 4 + 255) / 256, 256>>>((const float4*)Wi, (float4*)wip, EMB * GATES / 4);
    pack_wo_k<<<(int)(((long long)VOC * HID + 255) / 256), 256>>>(Wo, wopk);
    pack_wh_k<<<(128 * 8 * 3 * 8 * 32) / 256, 256>>>(Wh, whp);
    gather_x_k<<<ROWS * 128 / 256, 256>>>((const float4*)embed, targets, (float4*)xt);

    // ---- 1) xW = x @ Wi + bi (legacy path) ----
    gemm_pipe<<<dim3(ROWS / 128, GATES / 128), 256, gemm_smem>>>(xt, wip, bi, xW, GATES, EMB);

    // ---- 2) GRU recurrence ----
    gru_rec<<<RNB, RNT, rec_smem>>>(enc, whp, bhn, xW);

    // ---- 3) logits = hs @ Wo + bo (fragment-packed legacy GEMM) ----
    gemm_big<<<dim3(ROWS / 128, VOC / 256), 256, GB_SMEM>>>(apk, wopk, bo, (float*)d_out);

    (void)out_size;
}

// round 16
// speedup vs baseline: 1.0009x; 1.0009x over previous
#include <cuda_runtime.h>
#include <cstdint>

#define BATCH 16
#define TLEN  256
#define HID   1024
#define EMB   512
#define VOC   32000
#define GATES 3072
#define ROWS  4096          // BATCH*TLEN

// ---------------- device scratch (no allocations allowed) ----------------
__device__ float g_xW[ROWS * GATES];        // 50.3 MB : x@Wi + bi (fp32)
__device__ float g_apk[ROWS * HID];         // 16.8 MB : hidden states, FRAGMENT-PACKED tf32
__device__ float g_h[2][BATCH * HID];       // double-buffered h (tf32 bits)
__device__ float g_xt[ROWS * EMB];          // 8.4 MB  : gathered embeddings, tf32
__device__ float g_wip[EMB * GATES];        // 6.3 MB  : Wi tf32
__device__ float g_wopk[VOC * HID];         // 131 MB  : Wo FRAGMENT-PACKED tf32
__device__ uint4 g_whp[128 * 8 * 3 * 8 * 32]; // 12.6 MB: Wh packed mma fragments
__device__ unsigned g_bar_count = 0;
__device__ volatile unsigned g_bar_release = 0;  // monotonic epoch

// ---------------- helpers ----------------
__device__ __forceinline__ unsigned f2tf32(float f) {
    unsigned u;
    asm("cvt.rna.tf32.f32 %0, %1;" : "=r"(u) : "f"(f));
    return u;
}
__device__ __forceinline__ void mma_tf32(float c[4], const unsigned a[4],
                                         unsigned b0, unsigned b1) {
    asm volatile(
        "mma.sync.aligned.m16n8k8.row.col.f32.tf32.tf32.f32 "
        "{%0,%1,%2,%3}, {%4,%5,%6,%7}, {%8,%9}, {%0,%1,%2,%3};"
        : "+f"(c[0]), "+f"(c[1]), "+f"(c[2]), "+f"(c[3])
        : "r"(a[0]), "r"(a[1]), "r"(a[2]), "r"(a[3]), "r"(b0), "r"(b1));
}
__device__ __forceinline__ void cp16(uint32_t dst, const void* src) {
    asm volatile("cp.async.cg.shared.global [%0], [%1], 16;" :: "r"(dst), "l"(src));
}
__device__ __forceinline__ unsigned ld_acq(volatile unsigned* p) {
    unsigned v;
    asm volatile("ld.global.acquire.gpu.b32 %0, [%1];" : "=r"(v) : "l"((unsigned*)p));
    return v;
}
__device__ __forceinline__ void st_rel(volatile unsigned* p, unsigned v) {
    asm volatile("st.global.release.gpu.b32 [%0], %1;" :: "l"((unsigned*)p), "r"(v));
}
__device__ __forceinline__ uint32_t smem_u32(const void* p) {
    return (uint32_t)__cvta_generic_to_shared(p);
}

// ---------------- fragment-packed layout indexers (big GEMM) ----------------
// A tile 128x32 per (tm,tk): chunk = [warpM(2)][lane(32)][64 words], lane-rotated.
__device__ __forceinline__ int apack_idx(int m, int k) {
    int tm = m >> 7, r = m & 127;
    int tk = k >> 5, kk = k & 31;
    int wM = r >> 6, r6 = r & 63;
    int mf = r6 >> 4, hf = (r6 >> 3) & 1, gd = r6 & 7;
    int ks = kk >> 3, c8 = kk & 7;
    int qd = c8 >> 2, tg = c8 & 3;
    int lane = gd * 4 + tg;
    int w = hf + 2 * qd;
    int swz = (ks * 16 + mf * 4 + lane * 4) & 63;
    return (((tm * 32 + tk) * 2 + wM) * 32 + lane) * 64 + swz + w;
}
// B tile 32x256 per (tn,tk): chunk = [warpN(4)][lane(32)][64 words], lane-rotated.
__device__ __forceinline__ int bpack_idx(int n, int k) {
    int tn = n >> 8, n8 = n & 255;
    int wN = n8 >> 6, n6 = n8 & 63;
    int nf = n6 >> 3, gd = n6 & 7;
    int kk = k & 31, tk = k >> 5;
    int ks = kk >> 3, c8 = kk & 7;
    int s = c8 >> 2, tg = c8 & 3;
    int lane = gd * 4 + tg;
    int nfp = nf >> 1;
    int w = (nf & 1) * 2 + s;
    int swz = (ks * 16 + nfp * 4 + lane * 4) & 63;
    return (((tn * 32 + tk) * 4 + wN) * 32 + lane) * 64 + swz + w;
}

// ---------------- prep kernels ----------------
__global__ void cvt_tf32_k(const float4* __restrict__ in, float4* __restrict__ out, int n4) {
    int i = blockIdx.x * 256 + threadIdx.x;
    if (i >= n4) return;
    float4 v = in[i];
    v.x = __uint_as_float(f2tf32(v.x));
    v.y = __uint_as_float(f2tf32(v.y));
    v.z = __uint_as_float(f2tf32(v.z));
    v.w = __uint_as_float(f2tf32(v.w));
    out[i] = v;
}

__global__ void gather_x_k(const float4* __restrict__ embed, const int* __restrict__ targets,
                           float4* __restrict__ xt) {
    int i = blockIdx.x * 256 + threadIdx.x;
    int m = i >> 7, e = i & 127;
    int row = __ldg(targets + m);
    float4 v = embed[(size_t)row * 128 + e];
    v.x = __uint_as_float(f2tf32(v.x));
    v.y = __uint_as_float(f2tf32(v.y));
    v.z = __uint_as_float(f2tf32(v.z));
    v.w = __uint_as_float(f2tf32(v.w));
    xt[(size_t)m * 128 + e] = v;
}

__global__ void pack_wh_k(const float* __restrict__ Wh, uint4* __restrict__ whp) {
    int c = blockIdx.x * 256 + threadIdx.x;
    int lane = c & 31, t1 = c >> 5;
    int sp = t1 & 7; t1 >>= 3;
    int j = t1 % 3; t1 /= 3;
    int kw = t1 & 7, nb = t1 >> 3;
    int tig = lane & 3, gid = lane >> 2;
    int n  = j * 1024 + nb * 8 + gid;
    int kb = kw * 128 + sp * 16 + tig;
    uint4 v;
    v.x = f2tf32(Wh[(size_t)kb * GATES + n]);
    v.y = f2tf32(Wh[(size_t)(kb + 4) * GATES + n]);
    v.z = f2tf32(Wh[(size_t)(kb + 8) * GATES + n]);
    v.w = f2tf32(Wh[(size_t)(kb + 12) * GATES + n]);
    whp[c] = v;
}

// Wo [H,V] row-major -> fragment-packed [tn][tk][warpN][lane][64] (tf32 bits)
__global__ void pack_wo_k(const float* __restrict__ Wo, float* __restrict__ Bpk) {
    long long i = (long long)blockIdx.x * 256 + threadIdx.x;   // 32.768M elems
    if (i >= (long long)VOC * HID) return;
    int k = (int)(i / VOC);
    int n = (int)(i - (long long)k * VOC);
    Bpk[bpack_idx(n, k)] = __uint_as_float(f2tf32(Wo[i]));
}

// ---------------------------------------------------------------------------
// Legacy pipelined tf32 GEMM (kept for the small xW GEMM, K=512)
// ---------------------------------------------------------------------------
#define ASZ 4608
#define BSZ 4224

__global__ __launch_bounds__(256) void gemm_pipe(
    const float* __restrict__ A, const float* __restrict__ B,
    const float* __restrict__ bias, float* __restrict__ C, int N, int K)
{
    extern __shared__ unsigned gsm[];
    unsigned* As = gsm;
    unsigned* Bs = gsm + 3 * ASZ;
    const uint32_t as_base = smem_u32(As);
    const uint32_t bs_base = smem_u32(Bs);

    const int t  = threadIdx.x;
    const int m0 = blockIdx.x * 128;
    const int n0 = blockIdx.y * 128;
    const int warp = t >> 5, lane = t & 31;
    const int gid = lane >> 2, tig = lane & 3;
    const int wm = (warp >> 2) * 64, wn = (warp & 3) * 32;
    const int ar  = t >> 3;
    const int ac  = (t & 7) * 4;
    const int bkr = t >> 5;
    const int bc  = (t & 31) * 4;
    const int NT = K / 32;

    float acc[4][4][4];
#pragma unroll
    for (int mf = 0; mf < 4; mf++)
#pragma unroll
        for (int nf = 0; nf < 4; nf++)
#pragma unroll
            for (int i = 0; i < 4; i++) acc[mf][nf][i] = 0.f;

#pragma unroll
    for (int pre = 0; pre < 2; pre++) {
        int k0 = pre * 32;
#pragma unroll
        for (int p = 0; p < 4; p++) {
            int r = ar + 32 * p;
            cp16(as_base + (uint32_t)(pre * ASZ + r * 36 + ac) * 4,
                 A + (size_t)(m0 + r) * K + k0 + ac);
        }
#pragma unroll
        for (int p = 0; p < 4; p++) {
            int kr = bkr + 8 * p;
            cp16(bs_base + (uint32_t)(pre * BSZ + kr * 132 + bc) * 4,
                 B + (size_t)(k0 + kr) * N + n0 + bc);
        }
        asm volatile("cp.async.commit_group;");
    }

    for (int kt = 0; kt < NT; kt++) {
        asm volatile("cp.async.wait_group 1;");
        __syncthreads();
        int ft = kt + 2;
        if (ft < NT) {
            int st = ft % 3, k0 = ft * 32;
#pragma unroll
            for (int p = 0; p < 4; p++) {
                int r = ar + 32 * p;
                cp16(as_base + (uint32_t)(st * ASZ + r * 36 + ac) * 4,
                     A + (size_t)(m0 + r) * K + k0 + ac);
            }
#pragma unroll
            for (int p = 0; p < 4; p++) {
                int kr = bkr + 8 * p;
                cp16(bs_base + (uint32_t)(st * BSZ + kr * 132 + bc) * 4,
                     B + (size_t)(k0 + kr) * N + n0 + bc);
            }
        }
        asm volatile("cp.async.commit_group;");

        const unsigned* Ab = As + (kt % 3) * ASZ;
        const unsigned* Bb = Bs + (kt % 3) * BSZ;
#pragma unroll
        for (int ks = 0; ks < 4; ks++) {
            const int kk = ks * 8;
            unsigned af[4][4], bf[4][2];
#pragma unroll
            for (int mf = 0; mf < 4; mf++) {
                int r = wm + mf * 16 + gid;
                af[mf][0] = Ab[r * 36 + kk + tig];
                af[mf][1] = Ab[(r + 8) * 36 + kk + tig];
                af[mf][2] = Ab[r * 36 + kk + tig + 4];
                af[mf][3] = Ab[(r + 8) * 36 + kk + tig + 4];
            }
#pragma unroll
            for (int nf = 0; nf < 4; nf++) {
                int cn = wn + nf * 8 + gid;
                bf[nf][0] = Bb[(kk + tig) * 132 + cn];
                bf[nf][1] = Bb[(kk + tig + 4) * 132 + cn];
            }
#pragma unroll
            for (int mf = 0; mf < 4; mf++)
#pragma unroll
                for (int nf = 0; nf < 4; nf++)
                    mma_tf32(acc[mf][nf], af[mf], bf[nf][0], bf[nf][1]);
        }
    }

#pragma unroll
    for (int mf = 0; mf < 4; mf++) {
        int row = m0 + wm + mf * 16 + gid;
#pragma unroll
        for (int nf = 0; nf < 4; nf++) {
            int col = n0 + wn + nf * 8 + tig * 2;
            float b0 = bias ? bias[col] : 0.f;
            float b1 = bias ? bias[col + 1] : 0.f;
            float2 v0 = make_float2(acc[mf][nf][0] + b0, acc[mf][nf][1] + b1);
            float2 v1 = make_float2(acc[mf][nf][2] + b0, acc[mf][nf][3] + b1);
            *reinterpret_cast<float2*>(C + (size_t)row * N + col)       = v0;
            *reinterpret_cast<float2*>(C + (size_t)(row + 8) * N + col) = v1;
        }
    }
}

// ---------------------------------------------------------------------------
// Big output GEMM, fragment-packed operands, LDS.128 fragment loads.
// C[4096,32000] = A[4096,1024] @ Wo + bo.  Block tile 128x256x32, 8 warps
// (2 M x 4 N), warp tile 64x64, acc 128 regs. 3-stage cp.async pipeline.
// ---------------------------------------------------------------------------
#define GB_ASTG 4096            // words per A stage (16KB)
#define GB_BSTG 8192            // words per B stage (32KB)
#define GB_STG  (GB_ASTG + GB_BSTG)
#define GB_SMEM (3 * GB_STG * 4)   // 147456 B
#define GB_NT   32              // 1024/32 k-tiles

__global__ __launch_bounds__(256, 1) void gemm_big(
    const float* __restrict__ Apk, const float* __restrict__ Bpk,
    const float* __restrict__ bias, float* __restrict__ C)
{
    extern __shared__ unsigned gbs[];
    const uint32_t sbase = smem_u32(gbs);

    const int tid  = threadIdx.x;
    const int lane = tid & 31;
    const int warp = tid >> 5;
    const int wM   = warp & 1;        // 0..1
    const int wN   = warp >> 1;       // 0..3
    const int mt   = blockIdx.x;      // 0..31
    const int nt   = blockIdx.y;      // 0..124

    float acc[4][8][4];
#pragma unroll
    for (int mf = 0; mf < 4; mf++)
#pragma unroll
        for (int nf = 0; nf < 8; nf++)
#pragma unroll
            for (int i = 0; i < 4; i++) acc[mf][nf][i] = 0.f;

    const float* abase = Apk + (size_t)(mt * 32) * GB_ASTG + tid * 16;
    const float* bbase = Bpk + (size_t)(nt * 32) * GB_BSTG + tid * 32;

    // prologue: stages 0,1
#pragma unroll
    for (int pre = 0; pre < 2; pre++) {
        uint32_t sa = sbase + (uint32_t)(pre * GB_STG + tid * 16) * 4;
        uint32_t sb = sbase + (uint32_t)(pre * GB_STG + GB_ASTG + tid * 32) * 4;
        const float* ga = abase + (size_t)pre * GB_ASTG;
        const float* gb = bbase + (size_t)pre * GB_BSTG;
#pragma unroll
        for (int j = 0; j < 4; j++) cp16(sa + j * 16, ga + j * 4);
#pragma unroll
        for (int j = 0; j < 8; j++) cp16(sb + j * 16, gb + j * 4);
        asm volatile("cp.async.commit_group;");
    }

    const int aoff = (wM * 32 + lane) * 64;
    const int boff = (wN * 32 + lane) * 64;
    const int rot  = lane * 4;

    for (int kt = 0; kt < GB_NT; kt++) {
        asm volatile("cp.async.wait_group 1;");
        __syncthreads();

        int ft = kt + 2;
        if (ft < GB_NT) {
            int st = ft % 3;
            uint32_t sa = sbase + (uint32_t)(st * GB_STG + tid * 16) * 4;
            uint32_t sb = sbase + (uint32_t)(st * GB_STG + GB_ASTG + tid * 32) * 4;
            const float* ga = abase + (size_t)ft * GB_ASTG;
            const float* gb = bbase + (size_t)ft * GB_BSTG;
#pragma unroll
            for (int j = 0; j < 4; j++) cp16(sa + j * 16, ga + j * 4);
#pragma unroll
            for (int j = 0; j < 8; j++) cp16(sb + j * 16, gb + j * 4);
        }
        asm volatile("cp.async.commit_group;");

        const unsigned* Ab = gbs + (kt % 3) * GB_STG + aoff;
        const unsigned* Bb = gbs + (kt % 3) * GB_STG + GB_ASTG + boff;

#pragma unroll
        for (int ks = 0; ks < 4; ks++) {
            uint4 av[4], bv[4];
#pragma unroll
            for (int mf = 0; mf < 4; mf++)
                av[mf] = *reinterpret_cast<const uint4*>(
                    Ab + ((ks * 16 + mf * 4 + rot) & 63));
#pragma unroll
            for (int np = 0; np < 4; np++)
                bv[np] = *reinterpret_cast<const uint4*>(
                    Bb + ((ks * 16 + np * 4 + rot) & 63));
#pragma unroll
            for (int mf = 0; mf < 4; mf++) {
                unsigned af[4] = {av[mf].x, av[mf].y, av[mf].z, av[mf].w};
#pragma unroll
                for (int np = 0; np < 4; np++) {
                    mma_tf32(acc[mf][2 * np],     af, bv[np].x, bv[np].y);
                    mma_tf32(acc[mf][2 * np + 1], af, bv[np].z, bv[np].w);
                }
            }
        }
    }

    // epilogue
    const int gid = lane >> 2, tig = lane & 3;
#pragma unroll
    for (int mf = 0; mf < 4; mf++) {
        int row = mt * 128 + wM * 64 + mf * 16 + gid;
        float* c0 = C + (size_t)row * VOC;
        float* c1 = C + (size_t)(row + 8) * VOC;
#pragma unroll
        for (int nf = 0; nf < 8; nf++) {
            int col = nt * 256 + wN * 64 + nf * 8 + tig * 2;
            float b0 = bias[col], b1 = bias[col + 1];
            *reinterpret_cast<float2*>(c0 + col) =
                make_float2(acc[mf][nf][0] + b0, acc[mf][nf][1] + b1);
            *reinterpret_cast<float2*>(c1 + col) =
                make_float2(acc[mf][nf][2] + b0, acc[mf][nf][3] + b1);
        }
    }
}

// ---------------------------------------------------------------------------
// Tensor-core GRU recurrence (tf32 h exchange, fp32 register carry).
// Writes hidden states directly in fragment-packed order for gemm_big.
// ---------------------------------------------------------------------------
#define RNB 128
#define RNT 256
#define HSH 1028
#define WGT_WORDS (8*3*8*32*4)
#define PART_STRIDE 9

__global__ __launch_bounds__(RNT) void gru_rec(
    const float* __restrict__ enc, const uint4* __restrict__ whp,
    const float* __restrict__ bhn, const float* __restrict__ xW)
{
    extern __shared__ unsigned smu[];
    unsigned* sh_wgt = smu;
    float* sh_h      = (float*)(smu + WGT_WORDS);
    float* sh_part   = sh_h + BATCH * HSH;

    const int tid  = threadIdx.x;
    const int warp = tid >> 5;
    const int lane = tid & 31;
    const int gid  = lane >> 2, tig = lane & 3;
    const int u0   = blockIdx.x * 8;

    {
        const uint4* src = whp + (size_t)blockIdx.x * (WGT_WORDS / 4);
        uint4* dst = (uint4*)sh_wgt;
        for (int i = tid; i < WGT_WORDS / 4; i += RNT) dst[i] = src[i];
    }
    for (int idx = tid; idx < BATCH * HID; idx += RNT)
        sh_h[(idx >> 10) * HSH + (idx & 1023)] =
            __uint_as_float(f2tf32(enc[idx]));

    float hreg = 0.f;
    const int ob = tid >> 3, ou = tid & 7;
    if (tid < 128) hreg = enc[ob * HID + u0 + ou];
    __syncthreads();

    unsigned a[16][4];
#pragma unroll
    for (int s = 0; s < 16; s++) {
        int k = warp * 128 + s * 8 + tig;
        a[s][0] = __float_as_uint(sh_h[gid * HSH + k]);
        a[s][1] = __float_as_uint(sh_h[(gid + 8) * HSH + k]);
        a[s][2] = __float_as_uint(sh_h[gid * HSH + k + 4]);
        a[s][3] = __float_as_uint(sh_h[(gid + 8) * HSH + k + 4]);
    }

    const uint4* wp = (const uint4*)sh_wgt + warp * (3 * 8 * 32);

    for (int t = 0; t < TLEN; t++) {
        float xr = 0.f, xz = 0.f, xn = 0.f;
        if (tid < 128) {
            const float* xrow = xW + (size_t)(ob * TLEN + t) * GATES;
            int j = u0 + ou;
            xr = __ldg(xrow + j);
            xz = __ldg(xrow + HID + j);
            xn = __ldg(xrow + 2 * HID + j);
        }

        float c[3][4];
#pragma unroll
        for (int j = 0; j < 3; j++)
#pragma unroll
            for (int i = 0; i < 4; i++) c[j][i] = 0.f;

#pragma unroll
        for (int j = 0; j < 3; j++)
#pragma unroll
            for (int sp = 0; sp < 8; sp++) {
                uint4 bv = wp[(j * 8 + sp) * 32 + lane];
                mma_tf32(c[j], a[2 * sp],     bv.x, bv.y);
                mma_tf32(c[j], a[2 * sp + 1], bv.z, bv.w);
            }

#pragma unroll
        for (int j = 0; j < 3; j++) {
            sh_part[((j * 16 + gid) * 8 + tig * 2)         * PART_STRIDE + warp] = c[j][0];
            sh_part[((j * 16 + gid) * 8 + tig * 2 + 1)     * PART_STRIDE + warp] = c[j][1];
            sh_part[((j * 16 + gid + 8) * 8 + tig * 2)     * PART_STRIDE + warp] = c[j][2];
            sh_part[((j * 16 + gid + 8) * 8 + tig * 2 + 1) * PART_STRIDE + warp] = c[j][3];
        }
        __syncthreads();

        if (tid < 128) {
            float hr = 0.f, hz = 0.f, hn = 0.f;
#pragma unroll
            for (int q = 0; q < 8; q++) {
                hr += sh_part[((0 * 16 + ob) * 8 + ou) * PART_STRIDE + q];
                hz += sh_part[((1 * 16 + ob) * 8 + ou) * PART_STRIDE + q];
                hn += sh_part[((2 * 16 + ob) * 8 + ou) * PART_STRIDE + q];
            }
            int j = u0 + ou;
            float r  = 1.f / (1.f + expf(-(xr + hr)));
            float z  = 1.f / (1.f + expf(-(xz + hz)));
            float nn = tanhf(xn + r * (hn + bhn[j]));
            float hnew = (1.f - z) * nn + z * hreg;
            hreg = hnew;
            float htf = __uint_as_float(f2tf32(hnew));
            g_apk[apack_idx(ob * TLEN + t, j)] = htf;   // fragment-packed
            g_h[t & 1][ob * HID + j] = htf;
        }
        if (t == TLEN - 1) break;

        // ---- grid barrier ----
        __threadfence();
        __syncthreads();
        if (tid == 0) {
            unsigned epoch = g_bar_release;
            unsigned old = atomicAdd(&g_bar_count, 1);
            if (old == gridDim.x - 1) {
                g_bar_count = 0;
                __threadfence();
                st_rel(&g_bar_release, epoch + 1);
            } else {
                while (ld_acq(&g_bar_release) == epoch) { }
            }
        }
        __syncthreads();

        // ---- all-gather h (tf32 bits), rebuild fragments ----
        const float4* src = reinterpret_cast<const float4*>(&g_h[t & 1][0]);
        for (int i = tid; i < BATCH * HID / 4; i += RNT) {
            float4 v = __ldcg(&src[i]);
            int b = i >> 8, kk = (i & 255) << 2;
            *reinterpret_cast<float4*>(&sh_h[b * HSH + kk]) = v;
        }
        __syncthreads();
#pragma unroll
        for (int s = 0; s < 16; s++) {
            int k = warp * 128 + s * 8 + tig;
            a[s][0] = __float_as_uint(sh_h[gid * HSH + k]);
            a[s][1] = __float_as_uint(sh_h[(gid + 8) * HSH + k]);
            a[s][2] = __float_as_uint(sh_h[gid * HSH + k + 4]);
            a[s][3] = __float_as_uint(sh_h[(gid + 8) * HSH + k + 4]);
        }
    }
}

// ---------------------------------------------------------------------------
extern "C" void kernel_launch(void* const* d_in, const int* in_sizes, int n_in,
                              void* d_out, int out_size)
{
    const float *enc = nullptr, *embed = nullptr, *Wi = nullptr, *Wh = nullptr;
    const float *bi = nullptr, *bhn = nullptr, *Wo = nullptr, *bo = nullptr;
    const int* targets = nullptr;

    for (int i = 0; i < n_in; i++) {
        switch (in_sizes[i]) {
            case BATCH * HID:  enc     = (const float*)d_in[i]; break;
            case BATCH * TLEN: targets = (const int*)  d_in[i]; break;
            case VOC * EMB:    embed   = (const float*)d_in[i]; break;
            case EMB * GATES:  Wi      = (const float*)d_in[i]; break;
            case HID * GATES:  Wh      = (const float*)d_in[i]; break;
            case GATES:        bi      = (const float*)d_in[i]; break;
            case HID:          bhn     = (const float*)d_in[i]; break;
            case HID * VOC:    Wo      = (const float*)d_in[i]; break;
            case VOC:          bo      = (const float*)d_in[i]; break;
            default: break;
        }
    }

    float *xW, *apk, *xt, *wip, *wopk;
    uint4* whp;
    cudaGetSymbolAddress((void**)&xW,   g_xW);
    cudaGetSymbolAddress((void**)&apk,  g_apk);
    cudaGetSymbolAddress((void**)&xt,   g_xt);
    cudaGetSymbolAddress((void**)&wip,  g_wip);
    cudaGetSymbolAddress((void**)&wopk, g_wopk);
    cudaGetSymbolAddress((void**)&whp,  g_whp);

    const int gemm_smem = 3 * (ASZ + BSZ) * 4;
    const int rec_smem  = (WGT_WORDS + BATCH * HSH + 384 * PART_STRIDE) * 4;
    cudaFuncSetAttribute(gemm_pipe, cudaFuncAttributeMaxDynamicSharedMemorySize, gemm_smem);
    cudaFuncSetAttribute(gru_rec,   cudaFuncAttributeMaxDynamicSharedMemorySize, rec_smem);
    cudaFuncSetAttribute(gemm_big,  cudaFuncAttributeMaxDynamicSharedMemorySize, GB_SMEM);

    // ---- prep ----
    cvt_tf32_k<<<(EMB * GATES / 4 + 255) / 256, 256>>>((const float4*)Wi, (float4*)wip, EMB * GATES / 4);
    pack_wo_k<<<(int)(((long long)VOC * HID + 255) / 256), 256>>>(Wo, wopk);
    pack_wh_k<<<(128 * 8 * 3 * 8 * 32) / 256, 256>>>(Wh, whp);
    gather_x_k<<<ROWS * 128 / 256, 256>>>((const float4*)embed, targets, (float4*)xt);

    // ---- 1) xW = x @ Wi + bi (legacy path) ----
    gemm_pipe<<<dim3(ROWS / 128, GATES / 128), 256, gemm_smem>>>(xt, wip, bi, xW, GATES, EMB);

    // ---- 2) GRU recurrence ----
    gru_rec<<<RNB, RNT, rec_smem>>>(enc, whp, bhn, xW);

    // ---- 3) logits = hs @ Wo + bo (fragment-packed legacy GEMM) ----
    gemm_big<<<dim3(ROWS / 128, VOC / 256), 256, GB_SMEM>>>(apk, wopk, bo, (float*)d_out);

    (void)out_size;
}

// round 17
// speedup vs baseline: 1.0039x; 1.0030x over previous
#include <cuda_runtime.h>
#include <cstdint>

#define BATCH 16
#define TLEN  256
#define HID   1024
#define EMB   512
#define VOC   32000
#define GATES 3072
#define ROWS  4096          // BATCH*TLEN

// ---------------- device scratch (no allocations allowed) ----------------
__device__ float g_xW[ROWS * GATES];        // 50.3 MB : x@Wi + bi (fp32)
__device__ float g_apk[ROWS * HID];         // 16.8 MB : hidden states, FRAGMENT-PACKED tf32
__device__ float g_h[2][BATCH * HID];       // double-buffered h (tf32 bits)
__device__ float g_xt[ROWS * EMB];          // 8.4 MB  : gathered embeddings, tf32
__device__ float g_wip[EMB * GATES];        // 6.3 MB  : Wi tf32
__device__ float g_wopk[VOC * HID];         // 131 MB  : Wo FRAGMENT-PACKED tf32
__device__ uint4 g_whp[128 * 8 * 3 * 8 * 32]; // 12.6 MB: Wh packed mma fragments
__device__ unsigned g_bar_count = 0;
__device__ volatile unsigned g_bar_release = 0;  // monotonic epoch

// ---------------- helpers ----------------
__device__ __forceinline__ unsigned f2tf32(float f) {
    unsigned u;
    asm("cvt.rna.tf32.f32 %0, %1;" : "=r"(u) : "f"(f));
    return u;
}
__device__ __forceinline__ void mma_tf32(float c[4], const unsigned a[4],
                                         unsigned b0, unsigned b1) {
    asm volatile(
        "mma.sync.aligned.m16n8k8.row.col.f32.tf32.tf32.f32 "
        "{%0,%1,%2,%3}, {%4,%5,%6,%7}, {%8,%9}, {%0,%1,%2,%3};"
        : "+f"(c[0]), "+f"(c[1]), "+f"(c[2]), "+f"(c[3])
        : "r"(a[0]), "r"(a[1]), "r"(a[2]), "r"(a[3]), "r"(b0), "r"(b1));
}
__device__ __forceinline__ void cp16(uint32_t dst, const void* src) {
    asm volatile("cp.async.cg.shared.global [%0], [%1], 16;" :: "r"(dst), "l"(src));
}
__device__ __forceinline__ unsigned ld_acq(volatile unsigned* p) {
    unsigned v;
    asm volatile("ld.global.acquire.gpu.b32 %0, [%1];" : "=r"(v) : "l"((unsigned*)p));
    return v;
}
__device__ __forceinline__ void st_rel(volatile unsigned* p, unsigned v) {
    asm volatile("st.global.release.gpu.b32 [%0], %1;" :: "l"((unsigned*)p), "r"(v));
}
__device__ __forceinline__ uint32_t smem_u32(const void* p) {
    return (uint32_t)__cvta_generic_to_shared(p);
}

// ---------------- fragment-packed layout indexers (big GEMM) ----------------
// A tile 128x32 per (tm,tk): chunk = [warpM(2)][lane(32)][64 words], lane-rotated.
__device__ __forceinline__ int apack_idx(int m, int k) {
    int tm = m >> 7, r = m & 127;
    int tk = k >> 5, kk = k & 31;
    int wM = r >> 6, r6 = r & 63;
    int mf = r6 >> 4, hf = (r6 >> 3) & 1, gd = r6 & 7;
    int ks = kk >> 3, c8 = kk & 7;
    int qd = c8 >> 2, tg = c8 & 3;
    int lane = gd * 4 + tg;
    int w = hf + 2 * qd;
    int swz = (ks * 16 + mf * 4 + lane * 4) & 63;
    return (((tm * 32 + tk) * 2 + wM) * 32 + lane) * 64 + swz + w;
}
// B tile 32x256 per (tn,tk): chunk = [warpN(4)][lane(32)][64 words], lane-rotated.
__device__ __forceinline__ int bpack_idx(int n, int k) {
    int tn = n >> 8, n8 = n & 255;
    int wN = n8 >> 6, n6 = n8 & 63;
    int nf = n6 >> 3, gd = n6 & 7;
    int kk = k & 31, tk = k >> 5;
    int ks = kk >> 3, c8 = kk & 7;
    int s = c8 >> 2, tg = c8 & 3;
    int lane = gd * 4 + tg;
    int nfp = nf >> 1;
    int w = (nf & 1) * 2 + s;
    int swz = (ks * 16 + nfp * 4 + lane * 4) & 63;
    return (((tn * 32 + tk) * 4 + wN) * 32 + lane) * 64 + swz + w;
}

// ---------------- prep kernels ----------------
__global__ void cvt_tf32_k(const float4* __restrict__ in, float4* __restrict__ out, int n4) {
    int i = blockIdx.x * 256 + threadIdx.x;
    if (i >= n4) return;
    float4 v = in[i];
    v.x = __uint_as_float(f2tf32(v.x));
    v.y = __uint_as_float(f2tf32(v.y));
    v.z = __uint_as_float(f2tf32(v.z));
    v.w = __uint_as_float(f2tf32(v.w));
    out[i] = v;
}

__global__ void gather_x_k(const float4* __restrict__ embed, const int* __restrict__ targets,
                           float4* __restrict__ xt) {
    int i = blockIdx.x * 256 + threadIdx.x;
    int m = i >> 7, e = i & 127;
    int row = __ldg(targets + m);
    float4 v = embed[(size_t)row * 128 + e];
    v.x = __uint_as_float(f2tf32(v.x));
    v.y = __uint_as_float(f2tf32(v.y));
    v.z = __uint_as_float(f2tf32(v.z));
    v.w = __uint_as_float(f2tf32(v.w));
    xt[(size_t)m * 128 + e] = v;
}

__global__ void pack_wh_k(const float* __restrict__ Wh, uint4* __restrict__ whp) {
    int c = blockIdx.x * 256 + threadIdx.x;
    int lane = c & 31, t1 = c >> 5;
    int sp = t1 & 7; t1 >>= 3;
    int j = t1 % 3; t1 /= 3;
    int kw = t1 & 7, nb = t1 >> 3;
    int tig = lane & 3, gid = lane >> 2;
    int n  = j * 1024 + nb * 8 + gid;
    int kb = kw * 128 + sp * 16 + tig;
    uint4 v;
    v.x = f2tf32(Wh[(size_t)kb * GATES + n]);
    v.y = f2tf32(Wh[(size_t)(kb + 4) * GATES + n]);
    v.z = f2tf32(Wh[(size_t)(kb + 8) * GATES + n]);
    v.w = f2tf32(Wh[(size_t)(kb + 12) * GATES + n]);
    whp[c] = v;
}

// Wo [H,V] row-major -> fragment-packed [tn][tk][warpN][lane][64] (tf32 bits)
__global__ void pack_wo_k(const float* __restrict__ Wo, float* __restrict__ Bpk) {
    long long i = (long long)blockIdx.x * 256 + threadIdx.x;   // 32.768M elems
    if (i >= (long long)VOC * HID) return;
    int k = (int)(i / VOC);
    int n = (int)(i - (long long)k * VOC);
    Bpk[bpack_idx(n, k)] = __uint_as_float(f2tf32(Wo[i]));
}

// ---------------------------------------------------------------------------
// Legacy pipelined tf32 GEMM (kept for the small xW GEMM, K=512)
// ---------------------------------------------------------------------------
#define ASZ 4608
#define BSZ 4224

__global__ __launch_bounds__(256) void gemm_pipe(
    const float* __restrict__ A, const float* __restrict__ B,
    const float* __restrict__ bias, float* __restrict__ C, int N, int K)
{
    extern __shared__ unsigned gsm[];
    unsigned* As = gsm;
    unsigned* Bs = gsm + 3 * ASZ;
    const uint32_t as_base = smem_u32(As);
    const uint32_t bs_base = smem_u32(Bs);

    const int t  = threadIdx.x;
    const int m0 = blockIdx.x * 128;
    const int n0 = blockIdx.y * 128;
    const int warp = t >> 5, lane = t & 31;
    const int gid = lane >> 2, tig = lane & 3;
    const int wm = (warp >> 2) * 64, wn = (warp & 3) * 32;
    const int ar  = t >> 3;
    const int ac  = (t & 7) * 4;
    const int bkr = t >> 5;
    const int bc  = (t & 31) * 4;
    const int NT = K / 32;

    float acc[4][4][4];
#pragma unroll
    for (int mf = 0; mf < 4; mf++)
#pragma unroll
        for (int nf = 0; nf < 4; nf++)
#pragma unroll
            for (int i = 0; i < 4; i++) acc[mf][nf][i] = 0.f;

#pragma unroll
    for (int pre = 0; pre < 2; pre++) {
        int k0 = pre * 32;
#pragma unroll
        for (int p = 0; p < 4; p++) {
            int r = ar + 32 * p;
            cp16(as_base + (uint32_t)(pre * ASZ + r * 36 + ac) * 4,
                 A + (size_t)(m0 + r) * K + k0 + ac);
        }
#pragma unroll
        for (int p = 0; p < 4; p++) {
            int kr = bkr + 8 * p;
            cp16(bs_base + (uint32_t)(pre * BSZ + kr * 132 + bc) * 4,
                 B + (size_t)(k0 + kr) * N + n0 + bc);
        }
        asm volatile("cp.async.commit_group;");
    }

    for (int kt = 0; kt < NT; kt++) {
        asm volatile("cp.async.wait_group 1;");
        __syncthreads();
        int ft = kt + 2;
        if (ft < NT) {
            int st = ft % 3, k0 = ft * 32;
#pragma unroll
            for (int p = 0; p < 4; p++) {
                int r = ar + 32 * p;
                cp16(as_base + (uint32_t)(st * ASZ + r * 36 + ac) * 4,
                     A + (size_t)(m0 + r) * K + k0 + ac);
            }
#pragma unroll
            for (int p = 0; p < 4; p++) {
                int kr = bkr + 8 * p;
                cp16(bs_base + (uint32_t)(st * BSZ + kr * 132 + bc) * 4,
                     B + (size_t)(k0 + kr) * N + n0 + bc);
            }
        }
        asm volatile("cp.async.commit_group;");

        const unsigned* Ab = As + (kt % 3) * ASZ;
        const unsigned* Bb = Bs + (kt % 3) * BSZ;
#pragma unroll
        for (int ks = 0; ks < 4; ks++) {
            const int kk = ks * 8;
            unsigned af[4][4], bf[4][2];
#pragma unroll
            for (int mf = 0; mf < 4; mf++) {
                int r = wm + mf * 16 + gid;
                af[mf][0] = Ab[r * 36 + kk + tig];
                af[mf][1] = Ab[(r + 8) * 36 + kk + tig];
                af[mf][2] = Ab[r * 36 + kk + tig + 4];
                af[mf][3] = Ab[(r + 8) * 36 + kk + tig + 4];
            }
#pragma unroll
            for (int nf = 0; nf < 4; nf++) {
                int cn = wn + nf * 8 + gid;
                bf[nf][0] = Bb[(kk + tig) * 132 + cn];
                bf[nf][1] = Bb[(kk + tig + 4) * 132 + cn];
            }
#pragma unroll
            for (int mf = 0; mf < 4; mf++)
#pragma unroll
                for (int nf = 0; nf < 4; nf++)
                    mma_tf32(acc[mf][nf], af[mf], bf[nf][0], bf[nf][1]);
        }
    }

#pragma unroll
    for (int mf = 0; mf < 4; mf++) {
        int row = m0 + wm + mf * 16 + gid;
#pragma unroll
        for (int nf = 0; nf < 4; nf++) {
            int col = n0 + wn + nf * 8 + tig * 2;
            float b0 = bias ? bias[col] : 0.f;
            float b1 = bias ? bias[col + 1] : 0.f;
            float2 v0 = make_float2(acc[mf][nf][0] + b0, acc[mf][nf][1] + b1);
            float2 v1 = make_float2(acc[mf][nf][2] + b0, acc[mf][nf][3] + b1);
            *reinterpret_cast<float2*>(C + (size_t)row * N + col)       = v0;
            *reinterpret_cast<float2*>(C + (size_t)(row + 8) * N + col) = v1;
        }
    }
}

// ---------------------------------------------------------------------------
// Big output GEMM, fragment-packed operands, LDS.128 fragment loads.
// C[4096,32000] = A[4096,1024] @ Wo + bo.  Block tile 128x256x32, 8 warps
// (2 M x 4 N), warp tile 64x64, acc 128 regs. 3-stage cp.async pipeline.
// ---------------------------------------------------------------------------
#define GB_ASTG 4096            // words per A stage (16KB)
#define GB_BSTG 8192            // words per B stage (32KB)
#define GB_STG  (GB_ASTG + GB_BSTG)
#define GB_SMEM (3 * GB_STG * 4)   // 147456 B
#define GB_NT   32              // 1024/32 k-tiles

__global__ __launch_bounds__(256, 1) void gemm_big(
    const float* __restrict__ Apk, const float* __restrict__ Bpk,
    const float* __restrict__ bias, float* __restrict__ C)
{
    extern __shared__ unsigned gbs[];
    const uint32_t sbase = smem_u32(gbs);

    const int tid  = threadIdx.x;
    const int lane = tid & 31;
    const int warp = tid >> 5;
    const int wM   = warp & 1;        // 0..1
    const int wN   = warp >> 1;       // 0..3
    const int mt   = blockIdx.x;      // 0..31
    const int nt   = blockIdx.y;      // 0..124

    float acc[4][8][4];
#pragma unroll
    for (int mf = 0; mf < 4; mf++)
#pragma unroll
        for (int nf = 0; nf < 8; nf++)
#pragma unroll
            for (int i = 0; i < 4; i++) acc[mf][nf][i] = 0.f;

    const float* abase = Apk + (size_t)(mt * 32) * GB_ASTG + tid * 16;
    const float* bbase = Bpk + (size_t)(nt * 32) * GB_BSTG + tid * 32;

    // prologue: stages 0,1
#pragma unroll
    for (int pre = 0; pre < 2; pre++) {
        uint32_t sa = sbase + (uint32_t)(pre * GB_STG + tid * 16) * 4;
        uint32_t sb = sbase + (uint32_t)(pre * GB_STG + GB_ASTG + tid * 32) * 4;
        const float* ga = abase + (size_t)pre * GB_ASTG;
        const float* gb = bbase + (size_t)pre * GB_BSTG;
#pragma unroll
        for (int j = 0; j < 4; j++) cp16(sa + j * 16, ga + j * 4);
#pragma unroll
        for (int j = 0; j < 8; j++) cp16(sb + j * 16, gb + j * 4);
        asm volatile("cp.async.commit_group;");
    }

    const int aoff = (wM * 32 + lane) * 64;
    const int boff = (wN * 32 + lane) * 64;
    const int rot  = lane * 4;

    for (int kt = 0; kt < GB_NT; kt++) {
        asm volatile("cp.async.wait_group 1;");
        __syncthreads();

        int ft = kt + 2;
        if (ft < GB_NT) {
            int st = ft % 3;
            uint32_t sa = sbase + (uint32_t)(st * GB_STG + tid * 16) * 4;
            uint32_t sb = sbase + (uint32_t)(st * GB_STG + GB_ASTG + tid * 32) * 4;
            const float* ga = abase + (size_t)ft * GB_ASTG;
            const float* gb = bbase + (size_t)ft * GB_BSTG;
#pragma unroll
            for (int j = 0; j < 4; j++) cp16(sa + j * 16, ga + j * 4);
#pragma unroll
            for (int j = 0; j < 8; j++) cp16(sb + j * 16, gb + j * 4);
        }
        asm volatile("cp.async.commit_group;");

        const unsigned* Ab = gbs + (kt % 3) * GB_STG + aoff;
        const unsigned* Bb = gbs + (kt % 3) * GB_STG + GB_ASTG + boff;

#pragma unroll
        for (int ks = 0; ks < 4; ks++) {
            uint4 av[4], bv[4];
#pragma unroll
            for (int mf = 0; mf < 4; mf++)
                av[mf] = *reinterpret_cast<const uint4*>(
                    Ab + ((ks * 16 + mf * 4 + rot) & 63));
#pragma unroll
            for (int np = 0; np < 4; np++)
                bv[np] = *reinterpret_cast<const uint4*>(
                    Bb + ((ks * 16 + np * 4 + rot) & 63));
#pragma unroll
            for (int mf = 0; mf < 4; mf++) {
                unsigned af[4] = {av[mf].x, av[mf].y, av[mf].z, av[mf].w};
#pragma unroll
                for (int np = 0; np < 4; np++) {
                    mma_tf32(acc[mf][2 * np],     af, bv[np].x, bv[np].y);
                    mma_tf32(acc[mf][2 * np + 1], af, bv[np].z, bv[np].w);
                }
            }
        }
    }

    // epilogue
    const int gid = lane >> 2, tig = lane & 3;
#pragma unroll
    for (int mf = 0; mf < 4; mf++) {
        int row = mt * 128 + wM * 64 + mf * 16 + gid;
        float* c0 = C + (size_t)row * VOC;
        float* c1 = C + (size_t)(row + 8) * VOC;
#pragma unroll
        for (int nf = 0; nf < 8; nf++) {
            int col = nt * 256 + wN * 64 + nf * 8 + tig * 2;
            float b0 = bias[col], b1 = bias[col + 1];
            *reinterpret_cast<float2*>(c0 + col) =
                make_float2(acc[mf][nf][0] + b0, acc[mf][nf][1] + b1);
            *reinterpret_cast<float2*>(c1 + col) =
                make_float2(acc[mf][nf][2] + b0, acc[mf][nf][3] + b1);
        }
    }
}

// ---------------------------------------------------------------------------
// Tensor-core GRU recurrence (tf32 h exchange, fp32 register carry).
// Writes hidden states directly in fragment-packed order for gemm_big.
// ---------------------------------------------------------------------------
#define RNB 128
#define RNT 256
#define HSH 1028
#define WGT_WORDS (8*3*8*32*4)
#define PART_STRIDE 9

__global__ __launch_bounds__(RNT) void gru_rec(
    const float* __restrict__ enc, const uint4* __restrict__ whp,
    const float* __restrict__ bhn, const float* __restrict__ xW)
{
    extern __shared__ unsigned smu[];
    unsigned* sh_wgt = smu;
    float* sh_h      = (float*)(smu + WGT_WORDS);
    float* sh_part   = sh_h + BATCH * HSH;

    const int tid  = threadIdx.x;
    const int warp = tid >> 5;
    const int lane = tid & 31;
    const int gid  = lane >> 2, tig = lane & 3;
    const int u0   = blockIdx.x * 8;

    {
        const uint4* src = whp + (size_t)blockIdx.x * (WGT_WORDS / 4);
        uint4* dst = (uint4*)sh_wgt;
        for (int i = tid; i < WGT_WORDS / 4; i += RNT) dst[i] = src[i];
    }
    for (int idx = tid; idx < BATCH * HID; idx += RNT)
        sh_h[(idx >> 10) * HSH + (idx & 1023)] =
            __uint_as_float(f2tf32(enc[idx]));

    float hreg = 0.f;
    const int ob = tid >> 3, ou = tid & 7;
    if (tid < 128) hreg = enc[ob * HID + u0 + ou];
    __syncthreads();

    unsigned a[16][4];
#pragma unroll
    for (int s = 0; s < 16; s++) {
        int k = warp * 128 + s * 8 + tig;
        a[s][0] = __float_as_uint(sh_h[gid * HSH + k]);
        a[s][1] = __float_as_uint(sh_h[(gid + 8) * HSH + k]);
        a[s][2] = __float_as_uint(sh_h[gid * HSH + k + 4]);
        a[s][3] = __float_as_uint(sh_h[(gid + 8) * HSH + k + 4]);
    }

    const uint4* wp = (const uint4*)sh_wgt + warp * (3 * 8 * 32);

    for (int t = 0; t < TLEN; t++) {
        float xr = 0.f, xz = 0.f, xn = 0.f;
        if (tid < 128) {
            const float* xrow = xW + (size_t)(ob * TLEN + t) * GATES;
            int j = u0 + ou;
            xr = __ldg(xrow + j);
            xz = __ldg(xrow + HID + j);
            xn = __ldg(xrow + 2 * HID + j);
        }

        float c[3][4];
#pragma unroll
        for (int j = 0; j < 3; j++)
#pragma unroll
            for (int i = 0; i < 4; i++) c[j][i] = 0.f;

#pragma unroll
        for (int j = 0; j < 3; j++)
#pragma unroll
            for (int sp = 0; sp < 8; sp++) {
                uint4 bv = wp[(j * 8 + sp) * 32 + lane];
                mma_tf32(c[j], a[2 * sp],     bv.x, bv.y);
                mma_tf32(c[j], a[2 * sp + 1], bv.z, bv.w);
            }

#pragma unroll
        for (int j = 0; j < 3; j++) {
            sh_part[((j * 16 + gid) * 8 + tig * 2)         * PART_STRIDE + warp] = c[j][0];
            sh_part[((j * 16 + gid) * 8 + tig * 2 + 1)     * PART_STRIDE + warp] = c[j][1];
            sh_part[((j * 16 + gid + 8) * 8 + tig * 2)     * PART_STRIDE + warp] = c[j][2];
            sh_part[((j * 16 + gid + 8) * 8 + tig * 2 + 1) * PART_STRIDE + warp] = c[j][3];
        }
        __syncthreads();

        if (tid < 128) {
            float hr = 0.f, hz = 0.f, hn = 0.f;
#pragma unroll
            for (int q = 0; q < 8; q++) {
                hr += sh_part[((0 * 16 + ob) * 8 + ou) * PART_STRIDE + q];
                hz += sh_part[((1 * 16 + ob) * 8 + ou) * PART_STRIDE + q];
                hn += sh_part[((2 * 16 + ob) * 8 + ou) * PART_STRIDE + q];
            }
            int j = u0 + ou;
            float r  = 1.f / (1.f + expf(-(xr + hr)));
            float z  = 1.f / (1.f + expf(-(xz + hz)));
            float nn = tanhf(xn + r * (hn + bhn[j]));
            float hnew = (1.f - z) * nn + z * hreg;
            hreg = hnew;
            float htf = __uint_as_float(f2tf32(hnew));
            g_apk[apack_idx(ob * TLEN + t, j)] = htf;   // fragment-packed
            g_h[t & 1][ob * HID + j] = htf;
        }
        if (t == TLEN - 1) break;

        // ---- grid barrier ----
        __threadfence();
        __syncthreads();
        if (tid == 0) {
            unsigned epoch = g_bar_release;
            unsigned old = atomicAdd(&g_bar_count, 1);
            if (old == gridDim.x - 1) {
                g_bar_count = 0;
                __threadfence();
                st_rel(&g_bar_release, epoch + 1);
            } else {
                while (ld_acq(&g_bar_release) == epoch) { }
            }
        }
        __syncthreads();

        // ---- all-gather h (tf32 bits), rebuild fragments ----
        const float4* src = reinterpret_cast<const float4*>(&g_h[t & 1][0]);
        for (int i = tid; i < BATCH * HID / 4; i += RNT) {
            float4 v = __ldcg(&src[i]);
            int b = i >> 8, kk = (i & 255) << 2;
            *reinterpret_cast<float4*>(&sh_h[b * HSH + kk]) = v;
        }
        __syncthreads();
#pragma unroll
        for (int s = 0; s < 16; s++) {
            int k = warp * 128 + s * 8 + tig;
            a[s][0] = __float_as_uint(sh_h[gid * HSH + k]);
            a[s][1] = __float_as_uint(sh_h[(gid + 8) * HSH + k]);
            a[s][2] = __float_as_uint(sh_h[gid * HSH + k + 4]);
            a[s][3] = __float_as_uint(sh_h[(gid + 8) * HSH + k + 4]);
        }
    }
}

// ---------------------------------------------------------------------------
extern "C" void kernel_launch(void* const* d_in, const int* in_sizes, int n_in,
                              void* d_out, int out_size)
{
    const float *enc = nullptr, *embed = nullptr, *Wi = nullptr, *Wh = nullptr;
    const float *bi = nullptr, *bhn = nullptr, *Wo = nullptr, *bo = nullptr;
    const int* targets = nullptr;

    for (int i = 0; i < n_in; i++) {
        switch (in_sizes[i]) {
            case BATCH * HID:  enc     = (const float*)d_in[i]; break;
            case BATCH * TLEN: targets = (const int*)  d_in[i]; break;
            case VOC * EMB:    embed   = (const float*)d_in[i]; break;
            case EMB * GATES:  Wi      = (const float*)d_in[i]; break;
            case HID * GATES:  Wh      = (const float*)d_in[i]; break;
            case GATES:        bi      = (const float*)d_in[i]; break;
            case HID:          bhn     = (const float*)d_in[i]; break;
            case HID * VOC:    Wo      = (const float*)d_in[i]; break;
            case VOC:          bo      = (const float*)d_in[i]; break;
            default: break;
        }
    }

    float *xW, *apk, *xt, *wip, *wopk;
    uint4* whp;
    cudaGetSymbolAddress((void**)&xW,   g_xW);
    cudaGetSymbolAddress((void**)&apk,  g_apk);
    cudaGetSymbolAddress((void**)&xt,   g_xt);
    cudaGetSymbolAddress((void**)&wip,  g_wip);
    cudaGetSymbolAddress((void**)&wopk, g_wopk);
    cudaGetSymbolAddress((void**)&whp,  g_whp);

    const int gemm_smem = 3 * (ASZ + BSZ) * 4;
    const int rec_smem  = (WGT_WORDS + BATCH * HSH + 384 * PART_STRIDE) * 4;
    cudaFuncSetAttribute(gemm_pipe, cudaFuncAttributeMaxDynamicSharedMemorySize, gemm_smem);
    cudaFuncSetAttribute(gru_rec,   cudaFuncAttributeMaxDynamicSharedMemorySize, rec_smem);
    cudaFuncSetAttribute(gemm_big,  cudaFuncAttributeMaxDynamicSharedMemorySize, GB_SMEM);

    // ---- prep ----
    cvt_tf32_k<<<(EMB * GATES / 4 + 255) / 256, 256>>>((const float4*)Wi, (float4*)wip, EMB * GATES / 4);
    pack_wo_k<<<(int)(((long long)VOC * HID + 255) / 256), 256>>>(Wo, wopk);
    pack_wh_k<<<(128 * 8 * 3 * 8 * 32) / 256, 256>>>(Wh, whp);
    gather_x_k<<<ROWS * 128 / 256, 256>>>((const float4*)embed, targets, (float4*)xt);

    // ---- 1) xW = x @ Wi + bi (legacy path) ----
    gemm_pipe<<<dim3(ROWS / 128, GATES / 128), 256, gemm_smem>>>(xt, wip, bi, xW, GATES, EMB);

    // ---- 2) GRU recurrence ----
    gru_rec<<<RNB, RNT, rec_smem>>>(enc, whp, bhn, xW);

    // ---- 3) logits = hs @ Wo + bo (fragment-packed legacy GEMM) ----
    gemm_big<<<dim3(ROWS / 128, VOC / 256), 256, GB_SMEM>>>(apk, wopk, bo, (float*)d_out);

    (void)out_size;
}